// round 11
// baseline (speedup 1.0000x reference)
#include <cuda_runtime.h>
#include <cstdint>

// Problem constants
#define N_S   32
#define E_DIM 512
#define C_DIM 64
#define O_DIM 128
#define HW    64
#define KK9   9
#define CKK   576               // C_DIM * 9
#define FILT_STRIDE 73728       // O_DIM * CKK

// Scratch (allocation-free rule: __device__ globals)
__device__ __align__(256) float g_filt[N_S * FILT_STRIDE];   // 9.44 MB
__device__ __align__(256) float g_c1b[N_S * O_DIM];

__device__ __forceinline__ uint32_t f2tf32(float x) {
    uint32_t r;
    asm("cvt.rna.tf32.f32 %0, %1;" : "=r"(r) : "f"(x));
    return r;
}

__device__ __forceinline__ void mma_tf32(float& d0, float& d1, float& d2, float& d3,
                                         uint32_t a0, uint32_t a1, uint32_t a2, uint32_t a3,
                                         uint32_t b0, uint32_t b1) {
    asm volatile(
        "mma.sync.aligned.m16n8k8.row.col.f32.tf32.tf32.f32 "
        "{%0,%1,%2,%3}, {%4,%5,%6,%7}, {%8,%9}, {%0,%1,%2,%3};"
        : "+f"(d0), "+f"(d1), "+f"(d2), "+f"(d3)
        : "r"(a0), "r"(a1), "r"(a2), "r"(a3), "r"(b0), "r"(b1));
}

// ---------------------------------------------------------------------------
// Kernel 1: c1_b[n][o] = emb[n] . b_weight[o] + b_bias[o]   (fp32, tiny)
// ---------------------------------------------------------------------------
__global__ void bias_gemm_kernel(const float* __restrict__ emb,
                                 const float* __restrict__ bw,
                                 const float* __restrict__ bb) {
    int t = blockIdx.x * blockDim.x + threadIdx.x;   // 0..4095
    int n = t & 31;
    int o = t >> 5;
    if (o >= O_DIM) return;
    const float* er = emb + n * E_DIM;
    const float* wr = bw + o * E_DIM;
    float acc = 0.f;
#pragma unroll 8
    for (int e = 0; e < E_DIM; e++) acc += er[e] * wr[e];
    g_c1b[n * O_DIM + o] = acc + bb[o];
}

// ---------------------------------------------------------------------------
// Kernel 2: g_filt[m=0..31][j=0..73727] = emb @ W^T + w_bias   (tf32 MMA)
// BM=32 (all samples), BN=256 cols, BK=32. HBM-bound on W (151 MB).
// ---------------------------------------------------------------------------
__global__ void __launch_bounds__(256) gen_filter_kernel(
    const float* __restrict__ emb, const float* __restrict__ Wm,
    const float* __restrict__ wb) {
    __shared__ float As[32][36];    // [m][k], pad->36: conflict-free frag reads
    __shared__ float Bs[256][36];   // [j][k]

    const int j0 = blockIdx.x << 8;
    const int tid = threadIdx.x;
    const int lane = tid & 31;
    const int wn = tid >> 5;          // warp -> 32-col slice
    const int ar = lane >> 2, ac = lane & 3;

    float acc[2][4][4];
#pragma unroll
    for (int a = 0; a < 2; a++)
#pragma unroll
        for (int b = 0; b < 4; b++)
#pragma unroll
            for (int c = 0; c < 4; c++) acc[a][b][c] = 0.f;

    for (int e0 = 0; e0 < E_DIM; e0 += 32) {
        __syncthreads();
        // A tile: 32x32 = 256 float4 (1 per thread)
        {
            int r = tid >> 3;
            int kv = (tid & 7) << 2;
            float4 v = *reinterpret_cast<const float4*>(emb + r * E_DIM + e0 + kv);
            As[r][kv + 0] = __uint_as_float(f2tf32(v.x));
            As[r][kv + 1] = __uint_as_float(f2tf32(v.y));
            As[r][kv + 2] = __uint_as_float(f2tf32(v.z));
            As[r][kv + 3] = __uint_as_float(f2tf32(v.w));
        }
        // B tile: 256x32 = 2048 float4 (8 per thread), streaming W
#pragma unroll
        for (int i = 0; i < 8; i++) {
            int idx4 = tid + (i << 8);
            int j = idx4 >> 3;
            int kv = (idx4 & 7) << 2;
            float4 v = *reinterpret_cast<const float4*>(Wm + (size_t)(j0 + j) * E_DIM + e0 + kv);
            Bs[j][kv + 0] = __uint_as_float(f2tf32(v.x));
            Bs[j][kv + 1] = __uint_as_float(f2tf32(v.y));
            Bs[j][kv + 2] = __uint_as_float(f2tf32(v.z));
            Bs[j][kv + 3] = __uint_as_float(f2tf32(v.w));
        }
        __syncthreads();

#pragma unroll
        for (int ks = 0; ks < 4; ks++) {
            const int kk = ks << 3;
            uint32_t a[2][4], b[4][2];
#pragma unroll
            for (int tm = 0; tm < 2; tm++) {
                int m0 = tm << 4;
                a[tm][0] = __float_as_uint(As[m0 + ar][kk + ac]);
                a[tm][1] = __float_as_uint(As[m0 + 8 + ar][kk + ac]);
                a[tm][2] = __float_as_uint(As[m0 + ar][kk + 4 + ac]);
                a[tm][3] = __float_as_uint(As[m0 + 8 + ar][kk + 4 + ac]);
            }
#pragma unroll
            for (int tn = 0; tn < 4; tn++) {
                int p0 = (wn << 5) + (tn << 3) + ar;
                b[tn][0] = __float_as_uint(Bs[p0][kk + ac]);
                b[tn][1] = __float_as_uint(Bs[p0][kk + 4 + ac]);
            }
#pragma unroll
            for (int tm = 0; tm < 2; tm++)
#pragma unroll
                for (int tn = 0; tn < 4; tn++)
                    mma_tf32(acc[tm][tn][0], acc[tm][tn][1], acc[tm][tn][2], acc[tm][tn][3],
                             a[tm][0], a[tm][1], a[tm][2], a[tm][3],
                             b[tn][0], b[tn][1]);
        }
    }

    // Epilogue: + w_bias, store fp32 to scratch
#pragma unroll
    for (int tm = 0; tm < 2; tm++) {
#pragma unroll
        for (int tn = 0; tn < 4; tn++) {
            int row = (tm << 4) + ar;
            int col = j0 + (wn << 5) + (tn << 3) + (ac << 1);
            float2 bias = *reinterpret_cast<const float2*>(wb + col);
            float2 v0 = make_float2(acc[tm][tn][0] + bias.x, acc[tm][tn][1] + bias.y);
            *reinterpret_cast<float2*>(g_filt + (size_t)row * FILT_STRIDE + col) = v0;
            float2 v1 = make_float2(acc[tm][tn][2] + bias.x, acc[tm][tn][3] + bias.y);
            *reinterpret_cast<float2*>(g_filt + (size_t)(row + 8) * FILT_STRIDE + col) = v1;
        }
    }
}

// ---------------------------------------------------------------------------
// Kernel 3: implicit-GEMM conv. Block = (n, 2 output rows).
// M=128 (O), N=128 (2 rows x 64 px), K=576 (C*9), KC=32 chunks.
// ---------------------------------------------------------------------------
__global__ void __launch_bounds__(256) conv_kernel(
    const float* __restrict__ img, float* __restrict__ out) {
    __shared__ float As[128][36];   // filter tile [o][k]
    __shared__ float Bs[128][36];   // im2col tile [p][k]
    __shared__ float c1b_s[O_DIM];

    const int n  = blockIdx.y;
    const int h0 = blockIdx.x << 1;
    const int tid = threadIdx.x;
    const int lane = tid & 31;
    const int warp = tid >> 5;
    const int wm = warp & 1;     // 2 M-groups of 64 rows
    const int wn = warp >> 1;    // 4 N-groups of 32 cols
    const int ar = lane >> 2, ac = lane & 3;

    if (tid < O_DIM) c1b_s[tid] = g_c1b[n * O_DIM + tid];

    const float* filt_n = g_filt + (size_t)n * FILT_STRIDE;
    const float* img_n  = img + (size_t)n * (C_DIM * HW * HW);

    float acc[4][4][4];
#pragma unroll
    for (int a = 0; a < 4; a++)
#pragma unroll
        for (int b = 0; b < 4; b++)
#pragma unroll
            for (int c = 0; c < 4; c++) acc[a][b][c] = 0.f;

    for (int k0 = 0; k0 < CKK; k0 += 32) {
        __syncthreads();
        // A: 128x32 = 1024 float4 (4 per thread); filt rows k-contiguous
#pragma unroll
        for (int i = 0; i < 4; i++) {
            int idx4 = tid + (i << 8);
            int o = idx4 >> 3;
            int kv = (idx4 & 7) << 2;
            float4 v = *reinterpret_cast<const float4*>(filt_n + (size_t)o * CKK + k0 + kv);
            As[o][kv + 0] = __uint_as_float(f2tf32(v.x));
            As[o][kv + 1] = __uint_as_float(f2tf32(v.y));
            As[o][kv + 2] = __uint_as_float(f2tf32(v.z));
            As[o][kv + 3] = __uint_as_float(f2tf32(v.w));
        }
        // B: im2col 128x32, scalar loads (shifted windows hit L1/L2)
#pragma unroll
        for (int i = 0; i < 16; i++) {
            int idx = tid + (i << 8);        // 0..4095
            int ql = idx >> 7;               // 0..31
            int nl = idx & 127;              // 0..127
            int q = k0 + ql;
            int c = q / 9;
            int s = q - c * 9;
            int dy = s / 3;
            int dx = s - dy * 3;
            int h = h0 + (nl >> 6) + dy - 1;
            int w = (nl & 63) + dx - 1;
            float v = 0.f;
            if ((unsigned)h < 64u && (unsigned)w < 64u)
                v = img_n[(c << 12) + (h << 6) + w];
            Bs[nl][ql] = __uint_as_float(f2tf32(v));
        }
        __syncthreads();

#pragma unroll
        for (int ks = 0; ks < 4; ks++) {
            const int kk = ks << 3;
            uint32_t a[4][4], b[4][2];
#pragma unroll
            for (int tm = 0; tm < 4; tm++) {
                int m0 = (wm << 6) + (tm << 4);
                a[tm][0] = __float_as_uint(As[m0 + ar][kk + ac]);
                a[tm][1] = __float_as_uint(As[m0 + 8 + ar][kk + ac]);
                a[tm][2] = __float_as_uint(As[m0 + ar][kk + 4 + ac]);
                a[tm][3] = __float_as_uint(As[m0 + 8 + ar][kk + 4 + ac]);
            }
#pragma unroll
            for (int tn = 0; tn < 4; tn++) {
                int p0 = (wn << 5) + (tn << 3) + ar;
                b[tn][0] = __float_as_uint(Bs[p0][kk + ac]);
                b[tn][1] = __float_as_uint(Bs[p0][kk + 4 + ac]);
            }
#pragma unroll
            for (int tm = 0; tm < 4; tm++)
#pragma unroll
                for (int tn = 0; tn < 4; tn++)
                    mma_tf32(acc[tm][tn][0], acc[tm][tn][1], acc[tm][tn][2], acc[tm][tn][3],
                             a[tm][0], a[tm][1], a[tm][2], a[tm][3],
                             b[tn][0], b[tn][1]);
        }
    }

    // Epilogue: + c1_b, full-sector float2 stores
    float* out_n = out + (size_t)n * (O_DIM * HW * HW);
#pragma unroll
    for (int tm = 0; tm < 4; tm++) {
#pragma unroll
        for (int tn = 0; tn < 4; tn++) {
            int o_lo = (wm << 6) + (tm << 4) + ar;
            int col = (wn << 5) + (tn << 3) + (ac << 1);   // 0..127
            int h = h0 + (col >> 6);
            int w = col & 63;
            float b0 = c1b_s[o_lo];
            float2 v0 = make_float2(acc[tm][tn][0] + b0, acc[tm][tn][1] + b0);
            *reinterpret_cast<float2*>(out_n + ((size_t)o_lo << 12) + (h << 6) + w) = v0;
            int o_hi = o_lo + 8;
            float b1 = c1b_s[o_hi];
            float2 v1 = make_float2(acc[tm][tn][2] + b1, acc[tm][tn][3] + b1);
            *reinterpret_cast<float2*>(out_n + ((size_t)o_hi << 12) + (h << 6) + w) = v1;
        }
    }
}

// ---------------------------------------------------------------------------
extern "C" void kernel_launch(void* const* d_in, const int* in_sizes, int n_in,
                              void* d_out, int out_size) {
    const float* emb   = (const float*)d_in[0];   // [32, 512]
    const float* img   = (const float*)d_in[1];   // [32, 64, 64, 64]
    const float* ww    = (const float*)d_in[2];   // [73728, 512]
    const float* wbias = (const float*)d_in[3];   // [73728]
    const float* bw    = (const float*)d_in[4];   // [128, 512]
    const float* bbias = (const float*)d_in[5];   // [128]
    float* out = (float*)d_out;                   // [32, 128, 64, 64]

    bias_gemm_kernel<<<16, 256>>>(emb, bw, bbias);
    gen_filter_kernel<<<FILT_STRIDE / 256, 256>>>(emb, ww, wbias);
    dim3 grid(32, 32);   // (h-tiles of 2 rows, n)
    conv_kernel<<<grid, 256>>>(img, out);
}